// round 11
// baseline (speedup 1.0000x reference)
#include <cuda_runtime.h>
#include <cuda_fp16.h>
#include <cstdint>

#define CDIM 128
#define KNB 7
#define TILE_M 128
#define P1_THREADS 256
#define MAX_BN (4 * 40962)

// Inter-kernel scratch: per-(b,node) sigmoid score.
__device__ float g_s[MAX_BN];

// ---------------------------------------------------------------------------
// Dynamic SMEM layout (bytes):
//   W    : fp16 transposed W1 (swizzled)          32 KB
//   A    : fp16 q tile (swizzled)                 32 KB
//   RAW  : fp32 staging buffer (cp.async target)  64 KB
// ---------------------------------------------------------------------------
#define OFF_W   0
#define OFF_A   32768
#define OFF_RAW 65536
#define OFF_B1  (OFF_RAW + 65536)
#define OFF_V   (OFF_B1 + 512)
#define SMEM_TOTAL (OFF_V + 512)   // 132,096 B -> 1 CTA/SM

__device__ __forceinline__ uint32_t smem_u32(const void* p) {
    uint32_t a;
    asm("{ .reg .u64 t; cvta.to.shared.u64 t, %1; cvt.u32.u64 %0, t; }" : "=r"(a) : "l"(p));
    return a;
}

// Swizzled byte offset inside a [128 rows][128 fp16] tile.
// Row = 256 B = 16 units of 16 B; unit index XORed with (row & 7) so
// ldmatrix's 8-row reads hit distinct 16B groups (conflict-free; verified R8-R10).
__device__ __forceinline__ uint32_t swz(int row, int k) {
    return (uint32_t)(row * 256 + ((((k >> 3) ^ (row & 7)) << 4) | ((k & 7) << 1)));
}

__device__ __forceinline__ void ldsm4(uint32_t r[4], uint32_t addr) {
    asm volatile("ldmatrix.sync.aligned.m8n8.x4.shared.b16 {%0,%1,%2,%3}, [%4];"
                 : "=r"(r[0]), "=r"(r[1]), "=r"(r[2]), "=r"(r[3]) : "r"(addr));
}

__device__ __forceinline__ void mma16816(float c[4], const uint32_t a[4],
                                         uint32_t b0, uint32_t b1) {
    asm volatile(
        "mma.sync.aligned.m16n8k16.row.col.f32.f16.f16.f32 "
        "{%0,%1,%2,%3}, {%4,%5,%6,%7}, {%8,%9}, {%0,%1,%2,%3};"
        : "+f"(c[0]), "+f"(c[1]), "+f"(c[2]), "+f"(c[3])
        : "r"(a[0]), "r"(a[1]), "r"(a[2]), "r"(a[3]), "r"(b0), "r"(b1));
}

__device__ __forceinline__ float tanh_a(float x) {
    float y; asm("tanh.approx.f32 %0, %1;" : "=f"(y) : "f"(x)); return y;
}

// Async-fetch one 128x128 fp32 q tile into RAW (zero-fill past BN) and commit.
__device__ __forceinline__ void fetch_tile(char* smem, const float* __restrict__ query,
                                           long tile, int BN) {
    const int tid = threadIdx.x;
    #pragma unroll
    for (int it = 0; it < 16; it++) {
        int i = tid + it * P1_THREADS;
        int row = i >> 5, c4 = (i & 31) * 4;
        long grow = tile * TILE_M + row;
        int ok = (grow < BN);
        const float* src = query + (ok ? grow * CDIM + c4 : 0);
        uint32_t dst = smem_u32(smem + OFF_RAW + row * 512 + c4 * 4);
        int sz = ok ? 16 : 0;
        asm volatile("cp.async.cg.shared.global [%0], [%1], 16, %2;"
                     :: "r"(dst), "l"(src), "r"(sz) : "memory");
    }
    asm volatile("cp.async.commit_group;" ::: "memory");
}

// ============================================================================
// Pass 1 (HMMA + cp.async pipeline):
//   s[row] = sigmoid( tanh(q[row]@W1 + b1) . V + bV )
// Persistent CTAs (1/SM). Per tile: wait async fp32 tile -> convert to fp16
// (swizzled) -> kick fetch of next tile -> MMA + fused epilogue (fetch hidden).
// ============================================================================
__global__ __launch_bounds__(P1_THREADS, 1)
void pass1_hmma(const float* __restrict__ query, const float* __restrict__ W1,
                const float* __restrict__ b1, const float* __restrict__ Vw,
                const float* __restrict__ bV, int BN)
{
    extern __shared__ char smem[];
    const uint32_t sb = smem_u32(smem);
    const int tid = threadIdx.x, lane = tid & 31, wrp = tid >> 5;

    // ---- One-time: W1 (full 64KB fp32) into RAW, then transposed fp16 W_t[d][c]
    float* tmpW = (float*)(smem + OFF_RAW);
    for (int i = tid; i < CDIM * CDIM / 4; i += P1_THREADS)
        ((float4*)tmpW)[i] = ((const float4*)W1)[i];
    if (tid < CDIM) {
        ((float*)(smem + OFF_B1))[tid] = b1[tid];
        ((float*)(smem + OFF_V))[tid]  = Vw[tid];
    }
    __syncthreads();
    for (int i = tid; i < CDIM * CDIM / 2; i += P1_THREADS) {
        int d = i >> 6, c = (i & 63) * 2;            // W_t[d][c] = W1[c][d]
        __half2 hp = __floats2half2_rn(tmpW[(c + 0) * CDIM + d],
                                       tmpW[(c + 1) * CDIM + d]);
        *(__half2*)(smem + OFF_W + swz(d, c)) = hp;
    }
    __syncthreads();

    const float* sB1 = (const float*)(smem + OFF_B1);
    const float* sV  = (const float*)(smem + OFF_V);
    const float bV0 = bV[0];

    // per-lane ldmatrix addressing components
    const int lrow = lane & 15;               // row within 16-row tile
    const int lkof = (lane >> 4) << 3;        // k offset (0 or 8)
    const int r0 = wrp * 16;                  // this warp's row base in tile
    const int cq = 2 * (lane & 3);            // this lane's col pair offset

    const long ntiles = (BN + TILE_M - 1) / TILE_M;

    if ((long)blockIdx.x < ntiles) fetch_tile(smem, query, blockIdx.x, BN);

    for (long tile = blockIdx.x; tile < ntiles; tile += gridDim.x) {
        // ---- RAW tile ready? Convert fp32 -> fp16 swizzled A.
        asm volatile("cp.async.wait_group 0;" ::: "memory");
        __syncthreads();
        #pragma unroll
        for (int it = 0; it < 16; it++) {
            int i = tid + it * P1_THREADS;
            int row = i >> 5, c4 = (i & 31) * 4;
            float4 q4 = *(const float4*)(smem + OFF_RAW + row * 512 + c4 * 4);
            __half2 h01 = __floats2half2_rn(q4.x, q4.y);
            __half2 h23 = __floats2half2_rn(q4.z, q4.w);
            uint2 pk;
            pk.x = *(uint32_t*)&h01;
            pk.y = *(uint32_t*)&h23;
            *(uint2*)(smem + OFF_A + swz(row, c4)) = pk;
        }
        __syncthreads();   // A ready; RAW free for next fetch

        // ---- Kick next tile's fetch; it overlaps the MMA below.
        long nxt = tile + gridDim.x;
        if (nxt < ntiles) fetch_tile(smem, query, nxt, BN);

        // ---- Full-width accumulator, b1 folded into init.
        float acc[16][4];
        #pragma unroll
        for (int t = 0; t < 16; t++) {
            float b0 = sB1[t * 8 + cq], b1v = sB1[t * 8 + cq + 1];
            acc[t][0] = b0; acc[t][1] = b1v;
            acc[t][2] = b0; acc[t][3] = b1v;
        }

        #pragma unroll
        for (int k0 = 0; k0 < CDIM; k0 += 16) {
            uint32_t a[4];
            ldsm4(a, sb + OFF_A + swz(r0 + lrow, k0 + lkof));
            #pragma unroll
            for (int tp = 0; tp < 8; tp++) {
                uint32_t bh[4];
                ldsm4(bh, sb + OFF_W + swz(tp * 16 + lrow, k0 + lkof));
                mma16816(acc[2 * tp],     a, bh[0], bh[2]);
                mma16816(acc[2 * tp + 1], a, bh[1], bh[3]);
            }
        }

        // ---- Epilogue: tanh . V, per-lane partials over this lane's 32 cols
        float zlo = 0.f, zhi = 0.f;
        #pragma unroll
        for (int t = 0; t < 16; t++) {
            float v0 = sV[t * 8 + cq], v1 = sV[t * 8 + cq + 1];
            zlo += tanh_a(acc[t][0]) * v0 + tanh_a(acc[t][1]) * v1;
            zhi += tanh_a(acc[t][2]) * v0 + tanh_a(acc[t][3]) * v1;
        }

        // Reduce across the 4 lanes sharing a row
        zlo += __shfl_xor_sync(0xffffffffu, zlo, 1);
        zlo += __shfl_xor_sync(0xffffffffu, zlo, 2);
        zhi += __shfl_xor_sync(0xffffffffu, zhi, 1);
        zhi += __shfl_xor_sync(0xffffffffu, zhi, 2);

        if ((lane & 3) == 0) {
            long rlo = tile * TILE_M + r0 + (lane >> 2);
            long rhi = rlo + 8;
            if (rlo < BN) {
                float z = zlo + bV0;
                g_s[rlo] = __fdividef(1.0f, 1.0f + __expf(-z));
            }
            if (rhi < BN) {
                float z = zhi + bV0;
                g_s[rhi] = __fdividef(1.0f, 1.0f + __expf(-z));
            }
        }
        __syncthreads();   // all LDSM of A done before next convert overwrites
    }
}

// ============================================================================
// Pass 2: one warp per (b,n). All gathers issued up front for max MLP;
// streaming stores (no reuse) keep L2 free for the values working set.
// Lane l owns channels 4l..4l+3.
// ============================================================================
__global__ __launch_bounds__(256)
void pass2_kernel(const float* __restrict__ values, const int* __restrict__ neigh,
                  float* __restrict__ ctx, float* __restrict__ score,
                  int BN, int N)
{
    int gw = blockIdx.x * 8 + (threadIdx.x >> 5);
    if (gw >= BN) return;
    const int lane = threadIdx.x & 31;
    const int b = gw / N;
    const int n = gw - b * N;

    const int* nb = neigh + (long)n * KNB;
    int ix[KNB];
    #pragma unroll
    for (int k = 0; k < KNB; k++) ix[k] = __ldg(nb + k);

    // Issue the long-latency gathers first, all independent.
    const float* vb = values + (long)b * N * CDIM;
    float4 v4[KNB];
    #pragma unroll
    for (int k = 0; k < KNB; k++)
        v4[k] = *(const float4*)(vb + (long)ix[k] * CDIM + 4 * lane);

    float sk[KNB];
    #pragma unroll
    for (int k = 0; k < KNB; k++) sk[k] = g_s[b * N + ix[k]];

    float sum = 0.f;
    #pragma unroll
    for (int k = 0; k < KNB; k++) sum += sk[k];
    float inv = __fdividef(1.0f, sum);

    // score output is the raw sigmoid (pre-normalization), per reference.
    if (lane < KNB) __stcs(score + (long)gw * KNB + lane, sk[lane]);

    float4 a = make_float4(0.f, 0.f, 0.f, 0.f);
    #pragma unroll
    for (int k = 0; k < KNB; k++) {
        float w = sk[k] * inv;
        a.x += w * v4[k].x; a.y += w * v4[k].y;
        a.z += w * v4[k].z; a.w += w * v4[k].w;
    }
    __stcs((float4*)(ctx + (long)gw * CDIM + 4 * lane), a);
}

// ============================================================================
// Launch
// ============================================================================
extern "C" void kernel_launch(void* const* d_in, const int* in_sizes, int n_in,
                              void* d_out, int out_size)
{
    const float* query  = (const float*)d_in[0];
    const float* values = (const float*)d_in[1];
    const int*   neigh  = (const int*)d_in[2];
    const float* W1     = (const float*)d_in[3];
    const float* b1     = (const float*)d_in[4];
    const float* Vw     = (const float*)d_in[5];
    const float* bV     = (const float*)d_in[6];

    const int BN = in_sizes[0] / CDIM;   // B*N
    const int N  = in_sizes[2] / KNB;    // nodes

    float* ctx   = (float*)d_out;
    float* score = (float*)d_out + (size_t)BN * CDIM;

    int nsm = 148;
    cudaDeviceGetAttribute(&nsm, cudaDevAttrMultiProcessorCount, 0);

    cudaFuncSetAttribute(pass1_hmma, cudaFuncAttributeMaxDynamicSharedMemorySize, SMEM_TOTAL);
    pass1_hmma<<<nsm, P1_THREADS, SMEM_TOTAL>>>(query, W1, b1, Vw, bV, BN);

    int p2_blocks = (BN + 7) / 8;
    pass2_kernel<<<p2_blocks, 256>>>(values, neigh, ctx, score, BN, N);
}

// round 13
// speedup vs baseline: 1.1154x; 1.1154x over previous
#include <cuda_runtime.h>
#include <cuda_fp16.h>
#include <cstdint>

#define CDIM 128
#define KNB 7
#define TILE_M 128
#define P1_THREADS 256
#define MAX_BN (4 * 40962)

// Inter-kernel scratch: per-(b,node) sigmoid score + fp16 copy of values.
__device__ float  g_s[MAX_BN];
__device__ __half g_v[(size_t)MAX_BN * CDIM];

// ---------------------------------------------------------------------------
// Dynamic SMEM layout (bytes): W (fp16, transposed, swizzled) + A (fp16 tile)
// A region doubles as fp32 staging scratch for the one-time W transpose.
// ---------------------------------------------------------------------------
#define OFF_W  0
#define OFF_A  32768
#define OFF_B1 (OFF_A + 32768)
#define OFF_V  (OFF_B1 + 512)
#define SMEM_TOTAL (OFF_V + 512)   // 66,560 B -> 2 CTAs/SM

__device__ __forceinline__ uint32_t smem_u32(const void* p) {
    uint32_t a;
    asm("{ .reg .u64 t; cvta.to.shared.u64 t, %1; cvt.u32.u64 %0, t; }" : "=r"(a) : "l"(p));
    return a;
}

// Swizzled byte offset inside a [128 rows][128 fp16] tile.
// Row = 256 B = 16 units of 16 B; unit index XORed with (row & 7) so
// ldmatrix's 8-row reads hit distinct 16B groups (conflict-free; verified R8-R10).
__device__ __forceinline__ uint32_t swz(int row, int k) {
    return (uint32_t)(row * 256 + ((((k >> 3) ^ (row & 7)) << 4) | ((k & 7) << 1)));
}

__device__ __forceinline__ void ldsm4(uint32_t r[4], uint32_t addr) {
    asm volatile("ldmatrix.sync.aligned.m8n8.x4.shared.b16 {%0,%1,%2,%3}, [%4];"
                 : "=r"(r[0]), "=r"(r[1]), "=r"(r[2]), "=r"(r[3]) : "r"(addr));
}

__device__ __forceinline__ void mma16816(float c[4], const uint32_t a[4],
                                         uint32_t b0, uint32_t b1) {
    asm volatile(
        "mma.sync.aligned.m16n8k16.row.col.f32.f16.f16.f32 "
        "{%0,%1,%2,%3}, {%4,%5,%6,%7}, {%8,%9}, {%0,%1,%2,%3};"
        : "+f"(c[0]), "+f"(c[1]), "+f"(c[2]), "+f"(c[3])
        : "r"(a[0]), "r"(a[1]), "r"(a[2]), "r"(a[3]), "r"(b0), "r"(b1));
}

__device__ __forceinline__ float tanh_a(float x) {
    float y; asm("tanh.approx.f32 %0, %1;" : "=f"(y) : "f"(x)); return y;
}

// ============================================================================
// Pass 1 (HMMA, R10 structure: 2 CTAs/SM give implicit staging/MMA overlap):
//   s[row] = sigmoid( tanh(q[row]@W1 + b1) . V + bV )
// Additionally converts this tile's `values` rows to fp16 (g_v) — the LDG
// latency is hidden by sibling warps'/CTA's MMA work; DRAM has headroom.
// ============================================================================
__global__ __launch_bounds__(P1_THREADS, 2)
void pass1_hmma(const float* __restrict__ query, const float* __restrict__ values,
                const float* __restrict__ W1, const float* __restrict__ b1,
                const float* __restrict__ Vw, const float* __restrict__ bV, int BN)
{
    extern __shared__ char smem[];
    const uint32_t sb = smem_u32(smem);
    const int tid = threadIdx.x, lane = tid & 31, wrp = tid >> 5;

    // ---- One-time: W1 -> transposed fp16 W_t[d][c] in two 64-row chunks,
    // using the A region as coalesced fp32 staging scratch.
    float* tmpW = (float*)(smem + OFF_A);   // 64 rows x 128 fp32 = 32 KB
    for (int half = 0; half < 2; half++) {
        for (int i = tid; i < 64 * CDIM / 4; i += P1_THREADS)
            ((float4*)tmpW)[i] = ((const float4*)(W1 + half * 64 * CDIM))[i];
        __syncthreads();
        for (int i = tid; i < CDIM * 32; i += P1_THREADS) {
            int d = i >> 5, r = (i & 31) * 2;        // local rows r, r+1
            __half2 hp = __floats2half2_rn(tmpW[(r + 0) * CDIM + d],
                                           tmpW[(r + 1) * CDIM + d]);
            *(__half2*)(smem + OFF_W + swz(d, half * 64 + r)) = hp;
        }
        __syncthreads();
    }
    if (tid < CDIM) {
        ((float*)(smem + OFF_B1))[tid] = b1[tid];
        ((float*)(smem + OFF_V))[tid]  = Vw[tid];
    }
    __syncthreads();

    const float* sB1 = (const float*)(smem + OFF_B1);
    const float* sV  = (const float*)(smem + OFF_V);
    const float bV0 = bV[0];

    // per-lane ldmatrix addressing components
    const int lrow = lane & 15;               // row within 16-row tile
    const int lkof = (lane >> 4) << 3;        // k offset (0 or 8)
    const int r0 = wrp * 16;                  // this warp's row base in tile
    const int cq = 2 * (lane & 3);            // this lane's col pair offset

    const int ntiles = (BN + TILE_M - 1) / TILE_M;

    for (int tile = blockIdx.x; tile < ntiles; tile += gridDim.x) {
        // ---- Stage A tile: q fp32 -> fp16 via LDG.128 + STS.64, swizzled
        #pragma unroll
        for (int it = 0; it < TILE_M * 32 / P1_THREADS; it++) {   // 16 iters
            int i = tid + it * P1_THREADS;
            int row = i >> 5, c4 = (i & 31) * 4;
            long grow = (long)tile * TILE_M + row;
            float4 q4 = make_float4(0.f, 0.f, 0.f, 0.f);
            if (grow < BN) q4 = *(const float4*)(query + grow * CDIM + c4);
            __half2 h01 = __floats2half2_rn(q4.x, q4.y);
            __half2 h23 = __floats2half2_rn(q4.z, q4.w);
            uint2 pk;
            pk.x = *(uint32_t*)&h01;
            pk.y = *(uint32_t*)&h23;
            *(uint2*)(smem + OFF_A + swz(row, c4)) = pk;
        }
        __syncthreads();

        // ---- Woven side-job: convert this tile's values rows to fp16 g_v.
        // Pure gmem->gmem; LDG stalls here are absorbed by other warps' MMAs.
        #pragma unroll
        for (int it = 0; it < TILE_M * 32 / P1_THREADS; it++) {
            int i = tid + it * P1_THREADS;
            int row = i >> 5, c4 = (i & 31) * 4;
            long grow = (long)tile * TILE_M + row;
            if (grow < BN) {
                float4 v4 = *(const float4*)(values + grow * CDIM + c4);
                __half2 h01 = __floats2half2_rn(v4.x, v4.y);
                __half2 h23 = __floats2half2_rn(v4.z, v4.w);
                uint2 pk;
                pk.x = *(uint32_t*)&h01;
                pk.y = *(uint32_t*)&h23;
                *(uint2*)(g_v + grow * CDIM + c4) = pk;
            }
        }

        // ---- Full-width accumulator, b1 folded into init.
        // acc[t][0..1] -> row lane/4,   cols t*8 + cq + {0,1}
        // acc[t][2..3] -> row lane/4+8, same cols
        float acc[16][4];
        #pragma unroll
        for (int t = 0; t < 16; t++) {
            float b0 = sB1[t * 8 + cq], b1v = sB1[t * 8 + cq + 1];
            acc[t][0] = b0; acc[t][1] = b1v;
            acc[t][2] = b0; acc[t][3] = b1v;
        }

        #pragma unroll
        for (int k0 = 0; k0 < CDIM; k0 += 16) {
            uint32_t a[4];
            ldsm4(a, sb + OFF_A + swz(r0 + lrow, k0 + lkof));
            #pragma unroll
            for (int tp = 0; tp < 8; tp++) {
                uint32_t bh[4];
                ldsm4(bh, sb + OFF_W + swz(tp * 16 + lrow, k0 + lkof));
                mma16816(acc[2 * tp],     a, bh[0], bh[2]);
                mma16816(acc[2 * tp + 1], a, bh[1], bh[3]);
            }
        }

        // ---- Epilogue: tanh . V, per-lane partials over this lane's 32 cols
        float zlo = 0.f, zhi = 0.f;
        #pragma unroll
        for (int t = 0; t < 16; t++) {
            float v0 = sV[t * 8 + cq], v1 = sV[t * 8 + cq + 1];
            zlo += tanh_a(acc[t][0]) * v0 + tanh_a(acc[t][1]) * v1;
            zhi += tanh_a(acc[t][2]) * v0 + tanh_a(acc[t][3]) * v1;
        }

        // Reduce across the 4 lanes sharing a row
        zlo += __shfl_xor_sync(0xffffffffu, zlo, 1);
        zlo += __shfl_xor_sync(0xffffffffu, zlo, 2);
        zhi += __shfl_xor_sync(0xffffffffu, zhi, 1);
        zhi += __shfl_xor_sync(0xffffffffu, zhi, 2);

        if ((lane & 3) == 0) {
            long rlo = (long)tile * TILE_M + r0 + (lane >> 2);
            long rhi = rlo + 8;
            if (rlo < BN) {
                float z = zlo + bV0;
                g_s[rlo] = __fdividef(1.0f, 1.0f + __expf(-z));
            }
            if (rhi < BN) {
                float z = zhi + bV0;
                g_s[rhi] = __fdividef(1.0f, 1.0f + __expf(-z));
            }
        }
        __syncthreads();   // all reads of A done before next tile overwrites
    }
}

// ============================================================================
// Pass 2: one warp per (b,n). Gathers fp16 values (halves L2 gather bytes vs
// fp32) + 7 scores, all loads issued up front for MLP. fp32 math, plain stores.
// Lane l owns channels 4l..4l+3.
// ============================================================================
__global__ __launch_bounds__(256)
void pass2_kernel(const int* __restrict__ neigh,
                  float* __restrict__ ctx, float* __restrict__ score,
                  int BN, int N)
{
    int gw = blockIdx.x * 8 + (threadIdx.x >> 5);
    if (gw >= BN) return;
    const int lane = threadIdx.x & 31;
    const int b = gw / N;
    const int n = gw - b * N;

    const int* nb = neigh + (long)n * KNB;
    int ix[KNB];
    #pragma unroll
    for (int k = 0; k < KNB; k++) ix[k] = __ldg(nb + k);

    // Issue the long-latency gathers first, all independent.
    const __half* vb = g_v + (size_t)b * N * CDIM;
    uint2 raw[KNB];
    #pragma unroll
    for (int k = 0; k < KNB; k++)
        raw[k] = *(const uint2*)(vb + (long)ix[k] * CDIM + 4 * lane);

    float sk[KNB];
    #pragma unroll
    for (int k = 0; k < KNB; k++) sk[k] = g_s[b * N + ix[k]];

    float sum = 0.f;
    #pragma unroll
    for (int k = 0; k < KNB; k++) sum += sk[k];
    float inv = __fdividef(1.0f, sum);

    // score output is the raw sigmoid (pre-normalization), per reference.
    if (lane < KNB) score[(long)gw * KNB + lane] = sk[lane];

    float4 a = make_float4(0.f, 0.f, 0.f, 0.f);
    #pragma unroll
    for (int k = 0; k < KNB; k++) {
        float w = sk[k] * inv;
        float2 f01 = __half22float2(*(__half2*)&raw[k].x);
        float2 f23 = __half22float2(*(__half2*)&raw[k].y);
        a.x += w * f01.x; a.y += w * f01.y;
        a.z += w * f23.x; a.w += w * f23.y;
    }
    *(float4*)(ctx + (long)gw * CDIM + 4 * lane) = a;
}

// ============================================================================
// Launch
// ============================================================================
extern "C" void kernel_launch(void* const* d_in, const int* in_sizes, int n_in,
                              void* d_out, int out_size)
{
    const float* query  = (const float*)d_in[0];
    const float* values = (const float*)d_in[1];
    const int*   neigh  = (const int*)d_in[2];
    const float* W1     = (const float*)d_in[3];
    const float* b1     = (const float*)d_in[4];
    const float* Vw     = (const float*)d_in[5];
    const float* bV     = (const float*)d_in[6];

    const int BN = in_sizes[0] / CDIM;   // B*N
    const int N  = in_sizes[2] / KNB;    // nodes

    float* ctx   = (float*)d_out;
    float* score = (float*)d_out + (size_t)BN * CDIM;

    int nsm = 148;
    cudaDeviceGetAttribute(&nsm, cudaDevAttrMultiProcessorCount, 0);

    cudaFuncSetAttribute(pass1_hmma, cudaFuncAttributeMaxDynamicSharedMemorySize, SMEM_TOTAL);
    pass1_hmma<<<2 * nsm, P1_THREADS, SMEM_TOTAL>>>(query, values, W1, b1, Vw, bV, BN);

    int p2_blocks = (BN + 7) / 8;
    pass2_kernel<<<p2_blocks, 256>>>(neigh, ctx, score, BN, N);
}

// round 14
// speedup vs baseline: 1.3046x; 1.1696x over previous
#include <cuda_runtime.h>
#include <cuda_fp16.h>
#include <cstdint>

#define CDIM 128
#define KNB 7
#define TILE_M 64
#define P1_THREADS 256
#define MAX_BN (4 * 40962)

// Inter-kernel scratch: per-(b,node) sigmoid score.
__device__ float g_s[MAX_BN];

// ---------------------------------------------------------------------------
// Dynamic SMEM layout (bytes): W (fp16 transposed, swizzled) 32K,
// A (fp16 64-row tile) 16K, zbuf (2 x 64 partial row sums), b1, V.
// Total ~50.7 KB -> 3 CTAs/SM.
// ---------------------------------------------------------------------------
#define OFF_W   0
#define OFF_A   32768
#define OFF_ZB  (OFF_A + 16384)
#define OFF_B1  (OFF_ZB + 512)
#define OFF_V   (OFF_B1 + 512)
#define SMEM_TOTAL (OFF_V + 512)   // 50,688 B

__device__ __forceinline__ uint32_t smem_u32(const void* p) {
    uint32_t a;
    asm("{ .reg .u64 t; cvta.to.shared.u64 t, %1; cvt.u32.u64 %0, t; }" : "=r"(a) : "l"(p));
    return a;
}

// Swizzled byte offset inside a [rows][128 fp16] tile (row*256 B).
// Unit index XORed with (row & 7): ldmatrix 8-row reads conflict-free
// (verified R8-R13).
__device__ __forceinline__ uint32_t swz(int row, int k) {
    return (uint32_t)(row * 256 + ((((k >> 3) ^ (row & 7)) << 4) | ((k & 7) << 1)));
}

__device__ __forceinline__ void ldsm4(uint32_t r[4], uint32_t addr) {
    asm volatile("ldmatrix.sync.aligned.m8n8.x4.shared.b16 {%0,%1,%2,%3}, [%4];"
                 : "=r"(r[0]), "=r"(r[1]), "=r"(r[2]), "=r"(r[3]) : "r"(addr));
}

__device__ __forceinline__ void mma16816(float c[4], const uint32_t a[4],
                                         uint32_t b0, uint32_t b1) {
    asm volatile(
        "mma.sync.aligned.m16n8k16.row.col.f32.f16.f16.f32 "
        "{%0,%1,%2,%3}, {%4,%5,%6,%7}, {%8,%9}, {%0,%1,%2,%3};"
        : "+f"(c[0]), "+f"(c[1]), "+f"(c[2]), "+f"(c[3])
        : "r"(a[0]), "r"(a[1]), "r"(a[2]), "r"(a[3]), "r"(b0), "r"(b1));
}

__device__ __forceinline__ float tanh_a(float x) {
    float y; asm("tanh.approx.f32 %0, %1;" : "=f"(y) : "f"(x)); return y;
}

// ============================================================================
// Pass 1 (HMMA): s[row] = sigmoid( tanh(q[row]@W1 + b1) . V + bV )
// TILE_M=64, 3 CTAs/SM (finer tiles: tail imbalance 15% -> 4%; 24 warps/SM).
// 8 warps = 4 row-groups (16 rows) x 2 col-halves (64 cols). Per-row z is
// combined across the two col-half warps via zbuf in smem.
// ============================================================================
__global__ __launch_bounds__(P1_THREADS, 3)
void pass1_hmma(const float* __restrict__ query, const float* __restrict__ W1,
                const float* __restrict__ b1, const float* __restrict__ Vw,
                const float* __restrict__ bV, int BN)
{
    extern __shared__ char smem[];
    const uint32_t sb = smem_u32(smem);
    const int tid = threadIdx.x, lane = tid & 31, wrp = tid >> 5;

    // ---- One-time: W1 -> transposed fp16 W_t[d][c], staged through the A
    // region (16 KB) in four 32-row chunks.
    float* tmpW = (float*)(smem + OFF_A);   // 32 rows x 128 fp32 = 16 KB
    for (int ch = 0; ch < 4; ch++) {
        for (int i = tid; i < 32 * CDIM / 4; i += P1_THREADS)
            ((float4*)tmpW)[i] = ((const float4*)(W1 + ch * 32 * CDIM))[i];
        __syncthreads();
        for (int i = tid; i < CDIM * 16; i += P1_THREADS) {
            int d = i >> 4, r = (i & 15) * 2;        // local rows r, r+1
            __half2 hp = __floats2half2_rn(tmpW[(r + 0) * CDIM + d],
                                           tmpW[(r + 1) * CDIM + d]);
            *(__half2*)(smem + OFF_W + swz(d, ch * 32 + r)) = hp;
        }
        __syncthreads();
    }
    if (tid < CDIM) {
        ((float*)(smem + OFF_B1))[tid] = b1[tid];
        ((float*)(smem + OFF_V))[tid]  = Vw[tid];
    }
    __syncthreads();

    const float* sB1 = (const float*)(smem + OFF_B1);
    const float* sV  = (const float*)(smem + OFF_V);
    float* zbuf = (float*)(smem + OFF_ZB);   // [2][64]
    const float bV0 = bV[0];

    // warp decomposition: row-group + col-half
    const int rg = wrp & 3;                   // 16-row group within tile
    const int chf = wrp >> 2;                 // column half (0: 0-63, 1: 64-127)
    const int lrow = lane & 15;
    const int lkof = (lane >> 4) << 3;
    const int cq = 2 * (lane & 3);
    const int r0 = rg * 16;

    const int ntiles = (BN + TILE_M - 1) / TILE_M;

    for (int tile = blockIdx.x; tile < ntiles; tile += gridDim.x) {
        // ---- Stage A tile: 64 rows of q, fp32 -> fp16, swizzled
        #pragma unroll
        for (int it = 0; it < TILE_M * 32 / P1_THREADS; it++) {   // 8 iters
            int i = tid + it * P1_THREADS;
            int row = i >> 5, c4 = (i & 31) * 4;
            long grow = (long)tile * TILE_M + row;
            float4 q4 = make_float4(0.f, 0.f, 0.f, 0.f);
            if (grow < BN) q4 = *(const float4*)(query + grow * CDIM + c4);
            __half2 h01 = __floats2half2_rn(q4.x, q4.y);
            __half2 h23 = __floats2half2_rn(q4.z, q4.w);
            uint2 pk;
            pk.x = *(uint32_t*)&h01;
            pk.y = *(uint32_t*)&h23;
            *(uint2*)(smem + OFF_A + swz(row, c4)) = pk;
        }
        __syncthreads();

        // ---- 16 rows x 64 cols accumulator, b1 folded into init.
        // acc[t][0..1] -> row r0+lane/4,   cols chf*64 + t*8 + cq + {0,1}
        // acc[t][2..3] -> row r0+lane/4+8, same cols
        float acc[8][4];
        #pragma unroll
        for (int t = 0; t < 8; t++) {
            float b0 = sB1[chf * 64 + t * 8 + cq];
            float b1v = sB1[chf * 64 + t * 8 + cq + 1];
            acc[t][0] = b0; acc[t][1] = b1v;
            acc[t][2] = b0; acc[t][3] = b1v;
        }

        #pragma unroll
        for (int k0 = 0; k0 < CDIM; k0 += 16) {
            uint32_t a[4];
            ldsm4(a, sb + OFF_A + swz(r0 + lrow, k0 + lkof));
            #pragma unroll
            for (int tp = 0; tp < 4; tp++) {
                uint32_t bh[4];
                ldsm4(bh, sb + OFF_W + swz(chf * 64 + tp * 16 + lrow, k0 + lkof));
                mma16816(acc[2 * tp],     a, bh[0], bh[2]);
                mma16816(acc[2 * tp + 1], a, bh[1], bh[3]);
            }
        }

        // ---- Epilogue: tanh . V partials over this lane's 16 cols (per row)
        float zlo = 0.f, zhi = 0.f;
        #pragma unroll
        for (int t = 0; t < 8; t++) {
            float v0 = sV[chf * 64 + t * 8 + cq];
            float v1 = sV[chf * 64 + t * 8 + cq + 1];
            zlo += tanh_a(acc[t][0]) * v0 + tanh_a(acc[t][1]) * v1;
            zhi += tanh_a(acc[t][2]) * v0 + tanh_a(acc[t][3]) * v1;
        }
        // Reduce across the 4 lanes sharing a row, stash per-col-half sums
        zlo += __shfl_xor_sync(0xffffffffu, zlo, 1);
        zlo += __shfl_xor_sync(0xffffffffu, zlo, 2);
        zhi += __shfl_xor_sync(0xffffffffu, zhi, 1);
        zhi += __shfl_xor_sync(0xffffffffu, zhi, 2);
        if ((lane & 3) == 0) {
            zbuf[chf * 64 + r0 + (lane >> 2)]     = zlo;
            zbuf[chf * 64 + r0 + (lane >> 2) + 8] = zhi;
        }
        __syncthreads();

        // ---- Finalize: combine the two col-halves, sigmoid, store
        if (tid < TILE_M) {
            long grow = (long)tile * TILE_M + tid;
            if (grow < BN) {
                float z = zbuf[tid] + zbuf[64 + tid] + bV0;
                g_s[grow] = __fdividef(1.0f, 1.0f + __expf(-z));
            }
        }
        __syncthreads();   // zbuf read + all LDSM(A) done before next overwrite
    }
}

// ============================================================================
// Pass 2: one warp per (b,n); fp32 values gather (R10 structure), chunked
// 4+3 value loads to cut live registers -> 6 blocks/SM. Lane l owns
// channels 4l..4l+3.
// ============================================================================
__global__ __launch_bounds__(256, 6)
void pass2_kernel(const float* __restrict__ values, const int* __restrict__ neigh,
                  float* __restrict__ ctx, float* __restrict__ score,
                  int BN, int N)
{
    int gw = blockIdx.x * 8 + (threadIdx.x >> 5);
    if (gw >= BN) return;
    const int lane = threadIdx.x & 31;
    const int b = gw / N;
    const int n = gw - b * N;

    const int* nb = neigh + (long)n * KNB;
    int ix[KNB];
    #pragma unroll
    for (int k = 0; k < KNB; k++) ix[k] = __ldg(nb + k);

    const float* vb = values + (long)b * N * CDIM;

    // Chunk 1: first 4 value rows in flight
    float4 t0 = *(const float4*)(vb + (long)ix[0] * CDIM + 4 * lane);
    float4 t1 = *(const float4*)(vb + (long)ix[1] * CDIM + 4 * lane);
    float4 t2 = *(const float4*)(vb + (long)ix[2] * CDIM + 4 * lane);
    float4 t3 = *(const float4*)(vb + (long)ix[3] * CDIM + 4 * lane);

    float sk[KNB];
    #pragma unroll
    for (int k = 0; k < KNB; k++) sk[k] = g_s[b * N + ix[k]];

    float sum = 0.f;
    #pragma unroll
    for (int k = 0; k < KNB; k++) sum += sk[k];
    float inv = __fdividef(1.0f, sum);

    // score output is the raw sigmoid (pre-normalization), per reference.
    if (lane < KNB) score[(long)gw * KNB + lane] = sk[lane];

    float4 a;
    {
        float w = sk[0] * inv;
        a.x = w * t0.x; a.y = w * t0.y; a.z = w * t0.z; a.w = w * t0.w;
    }
    {
        float w = sk[1] * inv;
        a.x += w * t1.x; a.y += w * t1.y; a.z += w * t1.z; a.w += w * t1.w;
    }
    // Chunk 2: last 3 rows (issued as chunk-1 registers retire)
    float4 t4 = *(const float4*)(vb + (long)ix[4] * CDIM + 4 * lane);
    float4 t5 = *(const float4*)(vb + (long)ix[5] * CDIM + 4 * lane);
    float4 t6 = *(const float4*)(vb + (long)ix[6] * CDIM + 4 * lane);
    {
        float w = sk[2] * inv;
        a.x += w * t2.x; a.y += w * t2.y; a.z += w * t2.z; a.w += w * t2.w;
    }
    {
        float w = sk[3] * inv;
        a.x += w * t3.x; a.y += w * t3.y; a.z += w * t3.z; a.w += w * t3.w;
    }
    {
        float w = sk[4] * inv;
        a.x += w * t4.x; a.y += w * t4.y; a.z += w * t4.z; a.w += w * t4.w;
    }
    {
        float w = sk[5] * inv;
        a.x += w * t5.x; a.y += w * t5.y; a.z += w * t5.z; a.w += w * t5.w;
    }
    {
        float w = sk[6] * inv;
        a.x += w * t6.x; a.y += w * t6.y; a.z += w * t6.z; a.w += w * t6.w;
    }
    *(float4*)(ctx + (long)gw * CDIM + 4 * lane) = a;
}

// ============================================================================
// Launch
// ============================================================================
extern "C" void kernel_launch(void* const* d_in, const int* in_sizes, int n_in,
                              void* d_out, int out_size)
{
    const float* query  = (const float*)d_in[0];
    const float* values = (const float*)d_in[1];
    const int*   neigh  = (const int*)d_in[2];
    const float* W1     = (const float*)d_in[3];
    const float* b1     = (const float*)d_in[4];
    const float* Vw     = (const float*)d_in[5];
    const float* bV     = (const float*)d_in[6];

    const int BN = in_sizes[0] / CDIM;   // B*N
    const int N  = in_sizes[2] / KNB;    // nodes

    float* ctx   = (float*)d_out;
    float* score = (float*)d_out + (size_t)BN * CDIM;

    int nsm = 148;
    cudaDeviceGetAttribute(&nsm, cudaDevAttrMultiProcessorCount, 0);

    cudaFuncSetAttribute(pass1_hmma, cudaFuncAttributeMaxDynamicSharedMemorySize, SMEM_TOTAL);
    pass1_hmma<<<3 * nsm, P1_THREADS, SMEM_TOTAL>>>(query, W1, b1, Vw, bV, BN);

    int p2_blocks = (BN + 7) / 8;
    pass2_kernel<<<p2_blocks, 256>>>(values, neigh, ctx, score, BN, N);
}